// round 8
// baseline (speedup 1.0000x reference)
#include <cuda_runtime.h>

// ---------------- problem constants ----------------
constexpr int B    = 8;
constexpr int L    = 512;
constexpr int HID  = 1024;
constexpr int H    = 16;
constexpr int HD   = 64;     // head dim
constexpr int TAB  = 129;    // 2*64+1 relative-position table rows
constexpr int BL   = B * L;  // 4096

// ---------------- device scratch ----------------
__device__ float g_Q[BL * HID];
__device__ float g_K[BL * HID];
__device__ float g_V[BL * HID];
__device__ float g_X[BL * HID];   // w1+w2 merged, [B,L,HID]

// =====================================================================
// tf32 helpers
// =====================================================================
__device__ __forceinline__ float tf32r(float x) {
    unsigned y;
    asm("cvt.rna.tf32.f32 %0, %1;" : "=r"(y) : "f"(x));
    return __uint_as_float(y);
}

__device__ __forceinline__ float4 tf32r4(float4 v) {
    return make_float4(tf32r(v.x), tf32r(v.y), tf32r(v.z), tf32r(v.w));
}

__device__ __forceinline__ void mma_tf32(float d[4], const float a[4], const float b[2]) {
    unsigned const* A = reinterpret_cast<unsigned const*>(a);
    unsigned const* Bp = reinterpret_cast<unsigned const*>(b);
    asm volatile(
        "mma.sync.aligned.m16n8k8.row.col.f32.tf32.tf32.f32 "
        "{%0,%1,%2,%3}, {%4,%5,%6,%7}, {%8,%9}, {%0,%1,%2,%3};"
        : "+f"(d[0]), "+f"(d[1]), "+f"(d[2]), "+f"(d[3])
        : "r"(A[0]), "r"(A[1]), "r"(A[2]), "r"(A[3]),
          "r"(Bp[0]), "r"(Bp[1]));
}

// =====================================================================
// GEMM v2: C[4096,1024] = A @ W^T + bias.
// Block tile 128m x 256n, BK=16, 256 thr = 8 warps (2m x 4n),
// warp tile 64x64 (4 mt x 8 nt). Double-buffered smem.
// Fragment traffic: 128 B/MMA (vs 192 in v1); 1 block/SM (no LDS sharing).
// =====================================================================
constexpr int BKS = 20;                    // k-stride pad (16 -> 20)
constexpr int GA  = 128 * BKS;             // A buffer floats
constexpr int GB  = 256 * BKS;             // B buffer floats
constexpr size_t GEMM_SMEM = (size_t)2 * (GA + GB) * 4;  // 61,440 B

__device__ __forceinline__ void gemm_body(
    const float* __restrict__ A, const float* __restrict__ W,
    const float* __restrict__ bias, float* __restrict__ C)
{
    extern __shared__ float dsm[];
    float* AsBase = dsm;            // [2][GA]
    float* BsBase = dsm + 2 * GA;   // [2][GB]

    const int tid  = threadIdx.x;
    const int m0   = blockIdx.y * 128;
    const int n0   = blockIdx.x * 256;
    const int lane = tid & 31;
    const int g    = lane >> 2;
    const int t    = lane & 3;
    const int warp = tid >> 5;
    const int wm   = warp >> 2;        // 0..1 (64 rows)
    const int wn   = warp & 3;         // 0..3 (64 cols)

    // load mapping: 4 threads per row, float4 each
    const int lr = tid >> 2;           // 0..63
    const int lc = (tid & 3) * 4;      // 0,4,8,12
    const float* Ap = A + (size_t)(m0 + lr) * HID + lc;
    const float* Wp = W + (size_t)(n0 + lr) * HID + lc;

    float acc[4][8][4];
#pragma unroll
    for (int i = 0; i < 4; i++)
#pragma unroll
        for (int j = 0; j < 8; j++)
#pragma unroll
            for (int r = 0; r < 4; r++) acc[i][j][r] = 0.f;

    float4 pa[2], pb[4];
#pragma unroll
    for (int j = 0; j < 2; j++)
        pa[j] = *reinterpret_cast<const float4*>(Ap + (size_t)(64 * j) * HID);
#pragma unroll
    for (int j = 0; j < 4; j++)
        pb[j] = *reinterpret_cast<const float4*>(Wp + (size_t)(64 * j) * HID);

    // prologue: stage tile 0 into buffer 0
#pragma unroll
    for (int j = 0; j < 2; j++)
        *reinterpret_cast<float4*>(AsBase + (lr + 64 * j) * BKS + lc) = tf32r4(pa[j]);
#pragma unroll
    for (int j = 0; j < 4; j++)
        *reinterpret_cast<float4*>(BsBase + (lr + 64 * j) * BKS + lc) = tf32r4(pb[j]);

    int buf = 0;
    for (int k0 = 0; k0 < HID; k0 += 16, buf ^= 1) {
        __syncthreads();

        const bool more = (k0 + 16 < HID);
        if (more) {
#pragma unroll
            for (int j = 0; j < 2; j++)
                pa[j] = *reinterpret_cast<const float4*>(Ap + (size_t)(64 * j) * HID + k0 + 16);
#pragma unroll
            for (int j = 0; j < 4; j++)
                pb[j] = *reinterpret_cast<const float4*>(Wp + (size_t)(64 * j) * HID + k0 + 16);
        }

        const float* As = AsBase + buf * GA;
        const float* Bs = BsBase + buf * GB;
#pragma unroll
        for (int ks = 0; ks < 2; ks++) {
            const int kc = ks * 8 + t;
            float afr[4][4], bfr[8][2];
#pragma unroll
            for (int mt = 0; mt < 4; mt++) {
                const int r = wm * 64 + mt * 16 + g;
                afr[mt][0] = As[(r    ) * BKS + kc];
                afr[mt][1] = As[(r + 8) * BKS + kc];
                afr[mt][2] = As[(r    ) * BKS + kc + 4];
                afr[mt][3] = As[(r + 8) * BKS + kc + 4];
            }
#pragma unroll
            for (int nt = 0; nt < 8; nt++) {
                const int n = wn * 64 + nt * 8 + g;
                bfr[nt][0] = Bs[n * BKS + kc];
                bfr[nt][1] = Bs[n * BKS + kc + 4];
            }
#pragma unroll
            for (int mt = 0; mt < 4; mt++)
#pragma unroll
                for (int nt = 0; nt < 8; nt++)
                    mma_tf32(acc[mt][nt], afr[mt], bfr[nt]);
        }

        if (more) {
            float* asd = AsBase + (buf ^ 1) * GA;
            float* bsd = BsBase + (buf ^ 1) * GB;
#pragma unroll
            for (int j = 0; j < 2; j++)
                *reinterpret_cast<float4*>(asd + (lr + 64 * j) * BKS + lc) = tf32r4(pa[j]);
#pragma unroll
            for (int j = 0; j < 4; j++)
                *reinterpret_cast<float4*>(bsd + (lr + 64 * j) * BKS + lc) = tf32r4(pb[j]);
        }
    }

#pragma unroll
    for (int mt = 0; mt < 4; mt++) {
        const int row0 = m0 + wm * 64 + mt * 16 + g;
#pragma unroll
        for (int nt = 0; nt < 8; nt++) {
            const int col = n0 + wn * 64 + nt * 8 + 2 * t;
            const float b0 = bias[col], b1 = bias[col + 1];
            float* c0 = C + (size_t)row0 * HID + col;
            float* c1 = C + (size_t)(row0 + 8) * HID + col;
            c0[0] = acc[mt][nt][0] + b0; c0[1] = acc[mt][nt][1] + b1;
            c1[0] = acc[mt][nt][2] + b0; c1[1] = acc[mt][nt][3] + b1;
        }
    }
}

__global__ __launch_bounds__(256) void gemm_qkv(
    const float* __restrict__ q_in, const float* __restrict__ k_in,
    const float* __restrict__ v_in,
    const float* __restrict__ Wq, const float* __restrict__ bq,
    const float* __restrict__ Wk, const float* __restrict__ bk,
    const float* __restrict__ Wv, const float* __restrict__ bv)
{
    if (blockIdx.z == 0)      gemm_body(q_in, Wq, bq, g_Q);
    else if (blockIdx.z == 1) gemm_body(k_in, Wk, bk, g_K);
    else                      gemm_body(v_in, Wv, bv, g_V);
}

__global__ __launch_bounds__(256) void gemm_out(
    const float* __restrict__ W, const float* __restrict__ bias,
    float* __restrict__ C)
{
    gemm_body(g_X, W, bias, C);
}

// =====================================================================
// Fused MMA attention v4: 16-q tiles, 256 threads (8 warps), 93 KB smem
// -> 2 blocks/SM. Q frags in regs; K/V tiles (128 rows) register-prefetched.
//
// SMEM (float offsets):
//  sQ  @ 0      [16][68] = 1088      (union region U, 3200 floats)
//  sP  @ 1088   [16][132] = 2112     (U)
//  sSb @ 0      [16][136] = 2176     (U, after sQ/sP dead)
//  sKV @ 3200   9792 floats: table_k[136][68] -> K tiles[128][68]
//               -> V tiles[128][72] -> table_v[136][72]
//  sS  @ 12992  [16][516] = 8256
//  sF  @ 21248  [16][516] bytes = 2064 floats
// =====================================================================
constexpr int AQ_OFF  = 0;
constexpr int AP_OFF  = 1088;
constexpr int AKV_OFF = 3200;
constexpr int AS_OFF  = 12992;
constexpr int AF_OFF  = 21248;
constexpr int ATT_TOTAL = 23312;
constexpr size_t ATT_BYTES = (size_t)ATT_TOTAL * 4;   // 93,248 B

__global__ __launch_bounds__(256, 2) void attn_fused_mma(
    const int* __restrict__ fm,
    const float* __restrict__ table_k,
    const float* __restrict__ table_v)
{
    extern __shared__ float smem[];
    float* sQ  = smem + AQ_OFF;        // [16][68]
    float* sP  = smem + AP_OFF;        // [16][132]
    float* sSb = smem;                 // [16][136] union
    float* sKV = smem + AKV_OFF;
    float* sS  = smem + AS_OFF;        // [16][516]
    unsigned char* sFb = reinterpret_cast<unsigned char*>(smem + AF_OFF);

    const int tid  = threadIdx.x;
    const int lane = tid & 31;
    const int warp = tid >> 5;         // 0..7
    const int g    = lane >> 2;
    const int t    = lane & 3;
    const int q0   = blockIdx.x * 16;
    const int h    = blockIdx.y;
    const int b    = blockIdx.z;

    // prefetch mapping: 128-row tile = 8 float4/thread
    const int pr  = tid >> 4;          // row base 0..15 (advance by 16)
    const int psg = (tid & 15) * 4;
    const float* gKb = g_K + (size_t)(b * L) * HID + h * HD;
    const float* gVb = g_V + (size_t)(b * L) * HID + h * HD;

    // ---------- stage 0 ----------
    {
        const int q = tid >> 4;
        const int dbase = (tid & 15) * 4;
        float4 v = *reinterpret_cast<const float4*>(
            g_Q + (size_t)(b * L + q0 + q) * HID + h * HD + dbase);
        *reinterpret_cast<float4*>(sQ + q * 68 + dbase) = tf32r4(v);
    }
    for (int i = tid; i < 136 * 16; i += 256) {
        const int r = i >> 4, sg = (i & 15) * 4;
        float4 v = make_float4(0.f, 0.f, 0.f, 0.f);
        if (r < TAB) v = *reinterpret_cast<const float4*>(table_k + r * 64 + sg);
        *reinterpret_cast<float4*>(sKV + r * 68 + sg) = tf32r4(v);
    }
    for (int i = tid; i < 16 * 128; i += 256) {
        const int q = i >> 7;
        const int kq = (i & 127) * 4;
        const int4 v = *reinterpret_cast<const int4*>(
            fm + (size_t)(b * L + q0 + q) * L + kq);
        uchar4 pk = make_uchar4((unsigned char)v.x, (unsigned char)v.y,
                                (unsigned char)v.z, (unsigned char)v.w);
        *reinterpret_cast<uchar4*>(sFb + q * 516 + kq) = pk;
    }

    // issue K tile-0 loads
    float4 pf[8];
#pragma unroll
    for (int j = 0; j < 8; j++)
        pf[j] = *reinterpret_cast<const float4*>(
            gKb + (size_t)(pr + 16 * j) * HID + psg);

    __syncthreads();

    // ---------- Q fragments (m16: rows g, g+8) ----------
    float qf[8][4];
#pragma unroll
    for (int ks = 0; ks < 8; ks++) {
        const int kb = ks * 8;
        qf[ks][0] = sQ[(g    ) * 68 + kb + t];
        qf[ks][1] = sQ[(g + 8) * 68 + kb + t];
        qf[ks][2] = sQ[(g    ) * 68 + kb + t + 4];
        qf[ks][3] = sQ[(g + 8) * 68 + kb + t + 4];
    }

    // ---------- P[16][129] = Q @ table_k^T ----------
    for (int n8 = warp; n8 < 17; n8 += 8) {
        const int nb = n8 * 8;
        float acc[4] = {0.f, 0.f, 0.f, 0.f};
#pragma unroll
        for (int ks = 0; ks < 8; ks++) {
            const int kb = ks * 8;
            float bb[2];
            bb[0] = sKV[(nb + g) * 68 + kb + t];
            bb[1] = sKV[(nb + g) * 68 + kb + t + 4];
            mma_tf32(acc, qf[ks], bb);
        }
        const int c0 = nb + 2 * t;
        if (c0 < TAB) {
            sP[(g    ) * 132 + c0] = acc[0];
            sP[(g + 8) * 132 + c0] = acc[2];
        }
        if (c0 + 1 < TAB) {
            sP[(g    ) * 132 + c0 + 1] = acc[1];
            sP[(g + 8) * 132 + c0 + 1] = acc[3];
        }
    }
    __syncthreads();   // table_k region free

    // ---------- scores: 4 K-tiles of 128 rows ----------
#pragma unroll 1
    for (int kt = 0; kt < 4; kt++) {
        // store prefetched K tile; issue next (K kt+1, or V0)
#pragma unroll
        for (int j = 0; j < 8; j++)
            *reinterpret_cast<float4*>(sKV + (pr + 16 * j) * 68 + psg) = tf32r4(pf[j]);
        if (kt < 3) {
#pragma unroll
            for (int j = 0; j < 8; j++)
                pf[j] = *reinterpret_cast<const float4*>(
                    gKb + (size_t)((kt + 1) * 128 + pr + 16 * j) * HID + psg);
        } else {
#pragma unroll
            for (int j = 0; j < 8; j++)
                pf[j] = *reinterpret_cast<const float4*>(
                    gVb + (size_t)(pr + 16 * j) * HID + psg);
        }
        __syncthreads();

#pragma unroll
        for (int jj = 0; jj < 2; jj++) {
            const int nb = (warp * 2 + jj) * 8;   // local col 0..127
            float acc[4] = {0.f, 0.f, 0.f, 0.f};
#pragma unroll
            for (int ks = 0; ks < 8; ks++) {
                const int kb = ks * 8;
                float bb[2];
                bb[0] = sKV[(nb + g) * 68 + kb + t];
                bb[1] = sKV[(nb + g) * 68 + kb + t + 4];
                mma_tf32(acc, qf[ks], bb);
            }
            const int kc = kt * 128 + nb + 2 * t;
            const int r0 = g, r1 = g + 8;
            const int t00 = sFb[r0 * 516 + kc], t01 = sFb[r0 * 516 + kc + 1];
            const int t10 = sFb[r1 * 516 + kc], t11 = sFb[r1 * 516 + kc + 1];
            sS[r0 * 516 + kc    ] = (acc[0] + sP[r0 * 132 + t00]) * 0.125f;
            sS[r0 * 516 + kc + 1] = (acc[1] + sP[r0 * 132 + t01]) * 0.125f;
            sS[r1 * 516 + kc    ] = (acc[2] + sP[r1 * 132 + t10]) * 0.125f;
            sS[r1 * 516 + kc + 1] = (acc[3] + sP[r1 * 132 + t11]) * 0.125f;
        }
        __syncthreads();
    }

    // ---------- softmax: 8 warps x 2 rows; zero buckets ----------
    for (int r = warp * 2; r < warp * 2 + 2; r++) {
        float* row = sS + r * 516;
        float m = -1e30f;
#pragma unroll
        for (int i = 0; i < 16; i++) m = fmaxf(m, row[lane + 32 * i]);
#pragma unroll
        for (int o = 16; o > 0; o >>= 1) m = fmaxf(m, __shfl_xor_sync(0xffffffffu, m, o));
        float e[16];
        float s = 0.f;
#pragma unroll
        for (int i = 0; i < 16; i++) {
            e[i] = __expf(row[lane + 32 * i] - m);
            s += e[i];
        }
#pragma unroll
        for (int o = 16; o > 0; o >>= 1) s += __shfl_xor_sync(0xffffffffu, s, o);
        const float inv = 1.f / s;
#pragma unroll
        for (int i = 0; i < 16; i++) row[lane + 32 * i] = tf32r(e[i] * inv);
    }
    for (int i = tid; i < 16 * 136; i += 256) sSb[i] = 0.f;
    __syncthreads();

    // ---------- w1 = attn @ V: 4 V-tiles of 128 rows ----------
    const int nbw = warp * 8;      // warp's 8 output cols
    float acc1[4] = {0.f, 0.f, 0.f, 0.f};
#pragma unroll 1
    for (int vt = 0; vt < 4; vt++) {
#pragma unroll
        for (int j = 0; j < 8; j++)
            *reinterpret_cast<float4*>(sKV + (pr + 16 * j) * 72 + psg) = tf32r4(pf[j]);
        if (vt < 3) {
#pragma unroll
            for (int j = 0; j < 8; j++)
                pf[j] = *reinterpret_cast<const float4*>(
                    gVb + (size_t)((vt + 1) * 128 + pr + 16 * j) * HID + psg);
        }
        __syncthreads();

        const float* aS = sS + vt * 128;
#pragma unroll
        for (int ks = 0; ks < 16; ks++) {
            const int kb = ks * 8;
            float a[4], bb[2];
            a[0] = aS[(g    ) * 516 + kb + t];
            a[1] = aS[(g + 8) * 516 + kb + t];
            a[2] = aS[(g    ) * 516 + kb + t + 4];
            a[3] = aS[(g + 8) * 516 + kb + t + 4];
            bb[0] = sKV[(kb + t    ) * 72 + nbw + g];
            bb[1] = sKV[(kb + t + 4) * 72 + nbw + g];
            mma_tf32(acc1, a, bb);
        }
        __syncthreads();
    }

    // ---------- bucket scatter + stage table_v ----------
    {
        const int q  = tid >> 4;
        const int kg = tid & 15;
        const unsigned char* fr = sFb + q * 516;
        const float* ar = sS + q * 516;
        float* sbq = sSb + q * 136;
#pragma unroll 4
        for (int i = 0; i < 32; i++) {
            const int k = i * 16 + kg;
            atomicAdd(&sbq[fr[k]], ar[k]);
        }
    }
    for (int i = tid; i < 136 * 16; i += 256) {
        const int r = i >> 4, sg = (i & 15) * 4;
        float4 v = make_float4(0.f, 0.f, 0.f, 0.f);
        if (r < TAB) v = *reinterpret_cast<const float4*>(table_v + r * 64 + sg);
        *reinterpret_cast<float4*>(sKV + r * 72 + sg) = tf32r4(v);
    }
    __syncthreads();

    // ---------- w2 = buckets @ table_v (17 k-steps) ----------
    float acc2[4] = {0.f, 0.f, 0.f, 0.f};
#pragma unroll
    for (int ks = 0; ks < 17; ks++) {
        const int kb = ks * 8;
        float a[4], bb[2];
        a[0] = tf32r(sSb[(g    ) * 136 + kb + t]);
        a[1] = tf32r(sSb[(g + 8) * 136 + kb + t]);
        a[2] = tf32r(sSb[(g    ) * 136 + kb + t + 4]);
        a[3] = tf32r(sSb[(g + 8) * 136 + kb + t + 4]);
        bb[0] = sKV[(kb + t    ) * 72 + nbw + g];
        bb[1] = sKV[(kb + t + 4) * 72 + nbw + g];
        mma_tf32(acc2, a, bb);
    }

    // ---------- store ----------
    {
        const int col = nbw + 2 * t;
        float2 o0 = make_float2(acc1[0] + acc2[0], acc1[1] + acc2[1]);
        float2 o1 = make_float2(acc1[2] + acc2[2], acc1[3] + acc2[3]);
        *reinterpret_cast<float2*>(
            g_X + (size_t)(b * L + q0 + g) * HID + h * HD + col) = o0;
        *reinterpret_cast<float2*>(
            g_X + (size_t)(b * L + q0 + g + 8) * HID + h * HD + col) = o1;
    }
}

// =====================================================================
// launch
// =====================================================================
extern "C" void kernel_launch(void* const* d_in, const int* in_sizes, int n_in,
                              void* d_out, int out_size)
{
    const float* query   = (const float*)d_in[0];
    const float* key     = (const float*)d_in[1];
    const float* value   = (const float*)d_in[2];
    const int*   fm      = (const int*)  d_in[3];
    const float* Wq      = (const float*)d_in[4];
    const float* bq      = (const float*)d_in[5];
    const float* Wk      = (const float*)d_in[6];
    const float* bk      = (const float*)d_in[7];
    const float* Wv      = (const float*)d_in[8];
    const float* bv      = (const float*)d_in[9];
    const float* Wo      = (const float*)d_in[10];
    const float* bo      = (const float*)d_in[11];
    const float* table_k = (const float*)d_in[12];
    const float* table_v = (const float*)d_in[13];
    float* out = (float*)d_out;

    cudaFuncSetAttribute(attn_fused_mma,
                         cudaFuncAttributeMaxDynamicSharedMemorySize, (int)ATT_BYTES);
    cudaFuncSetAttribute(gemm_qkv,
                         cudaFuncAttributeMaxDynamicSharedMemorySize, (int)GEMM_SMEM);
    cudaFuncSetAttribute(gemm_out,
                         cudaFuncAttributeMaxDynamicSharedMemorySize, (int)GEMM_SMEM);

    const dim3 gqkv(HID / 256, BL / 128, 3);  // (4, 32, 3)
    gemm_qkv<<<gqkv, 256, GEMM_SMEM>>>(query, key, value, Wq, bq, Wk, bk, Wv, bv);

    const dim3 gattn(L / 16, H, B);  // (32, 16, 8)
    attn_fused_mma<<<gattn, 256, ATT_BYTES>>>(fm, table_k, table_v);

    const dim3 gout(HID / 256, BL / 128);  // (4, 32)
    gemm_out<<<gout, 256, GEMM_SMEM>>>(Wo, bo, out);
}

// round 9
// speedup vs baseline: 1.1261x; 1.1261x over previous
#include <cuda_runtime.h>

// ---------------- problem constants ----------------
constexpr int B    = 8;
constexpr int L    = 512;
constexpr int HID  = 1024;
constexpr int H    = 16;
constexpr int HD   = 64;     // head dim
constexpr int TAB  = 129;    // 2*64+1 relative-position table rows
constexpr int BL   = B * L;  // 4096

// ---------------- device scratch ----------------
__device__ float g_Q[BL * HID];
__device__ float g_K[BL * HID];
__device__ float g_V[BL * HID];
__device__ float g_X[BL * HID];   // w1+w2 merged, [B,L,HID]

// =====================================================================
// tf32 helpers
// =====================================================================
__device__ __forceinline__ float tf32r(float x) {
    unsigned y;
    asm("cvt.rna.tf32.f32 %0, %1;" : "=r"(y) : "f"(x));
    return __uint_as_float(y);
}

__device__ __forceinline__ float4 tf32r4(float4 v) {
    return make_float4(tf32r(v.x), tf32r(v.y), tf32r(v.z), tf32r(v.w));
}

__device__ __forceinline__ void mma_tf32(float d[4], const float a[4], const float b[2]) {
    unsigned const* A = reinterpret_cast<unsigned const*>(a);
    unsigned const* Bp = reinterpret_cast<unsigned const*>(b);
    asm volatile(
        "mma.sync.aligned.m16n8k8.row.col.f32.tf32.tf32.f32 "
        "{%0,%1,%2,%3}, {%4,%5,%6,%7}, {%8,%9}, {%0,%1,%2,%3};"
        : "+f"(d[0]), "+f"(d[1]), "+f"(d[2]), "+f"(d[3])
        : "r"(A[0]), "r"(A[1]), "r"(A[2]), "r"(A[3]),
          "r"(Bp[0]), "r"(Bp[1]));
}

// =====================================================================
// GEMM v3: C[4096,1024] = A @ W^T + bias.
// Block tile 128m x 256n, BK=16, 512 thr = 16 warps (4m x 4n),
// warp tile 32x64 (2 mt x 8 nt, acc = 64 regs). Double-buffered smem.
// Same total LDS traffic as v2 but 16 warps/SM and ~120 regs/thread.
// =====================================================================
constexpr int BKS = 20;                    // k-stride pad (16 -> 20)
constexpr int GA  = 128 * BKS;             // A buffer floats (2560)
constexpr int GB  = 256 * BKS;             // B buffer floats (5120)
constexpr size_t GEMM_SMEM = (size_t)2 * (GA + GB) * 4;  // 61,440 B

__device__ __forceinline__ void gemm_body(
    const float* __restrict__ A, const float* __restrict__ W,
    const float* __restrict__ bias, float* __restrict__ C)
{
    extern __shared__ float dsm[];
    float* AsBase = dsm;            // [2][GA]
    float* BsBase = dsm + 2 * GA;   // [2][GB]

    const int tid  = threadIdx.x;
    const int m0   = blockIdx.y * 128;
    const int n0   = blockIdx.x * 256;
    const int lane = tid & 31;
    const int g    = lane >> 2;
    const int t    = lane & 3;
    const int warp = tid >> 5;         // 0..15
    const int wm   = warp >> 2;        // 0..3 (32 rows)
    const int wn   = warp & 3;         // 0..3 (64 cols)

    // load mapping: 4 threads per row, one float4 each
    const int lr = tid >> 2;           // 0..127
    const int lc = (tid & 3) * 4;      // 0,4,8,12
    const float* Ap = A + (size_t)(m0 + lr) * HID + lc;          // 1 float4
    const float* Wp0 = W + (size_t)(n0 + lr) * HID + lc;         // 2 float4
    const float* Wp1 = W + (size_t)(n0 + lr + 128) * HID + lc;

    float acc[2][8][4];
#pragma unroll
    for (int i = 0; i < 2; i++)
#pragma unroll
        for (int j = 0; j < 8; j++)
#pragma unroll
            for (int r = 0; r < 4; r++) acc[i][j][r] = 0.f;

    float4 pa, pb0, pb1;
    pa  = *reinterpret_cast<const float4*>(Ap);
    pb0 = *reinterpret_cast<const float4*>(Wp0);
    pb1 = *reinterpret_cast<const float4*>(Wp1);

    // prologue: stage tile 0 into buffer 0
    *reinterpret_cast<float4*>(AsBase + lr * BKS + lc) = tf32r4(pa);
    *reinterpret_cast<float4*>(BsBase + lr * BKS + lc) = tf32r4(pb0);
    *reinterpret_cast<float4*>(BsBase + (lr + 128) * BKS + lc) = tf32r4(pb1);

    int buf = 0;
    for (int k0 = 0; k0 < HID; k0 += 16, buf ^= 1) {
        __syncthreads();

        const bool more = (k0 + 16 < HID);
        if (more) {
            pa  = *reinterpret_cast<const float4*>(Ap  + k0 + 16);
            pb0 = *reinterpret_cast<const float4*>(Wp0 + k0 + 16);
            pb1 = *reinterpret_cast<const float4*>(Wp1 + k0 + 16);
        }

        const float* As = AsBase + buf * GA;
        const float* Bs = BsBase + buf * GB;
#pragma unroll
        for (int ks = 0; ks < 2; ks++) {
            const int kc = ks * 8 + t;
            float afr[2][4], bfr[8][2];
#pragma unroll
            for (int mt = 0; mt < 2; mt++) {
                const int r = wm * 32 + mt * 16 + g;
                afr[mt][0] = As[(r    ) * BKS + kc];
                afr[mt][1] = As[(r + 8) * BKS + kc];
                afr[mt][2] = As[(r    ) * BKS + kc + 4];
                afr[mt][3] = As[(r + 8) * BKS + kc + 4];
            }
#pragma unroll
            for (int nt = 0; nt < 8; nt++) {
                const int n = wn * 64 + nt * 8 + g;
                bfr[nt][0] = Bs[n * BKS + kc];
                bfr[nt][1] = Bs[n * BKS + kc + 4];
            }
#pragma unroll
            for (int mt = 0; mt < 2; mt++)
#pragma unroll
                for (int nt = 0; nt < 8; nt++)
                    mma_tf32(acc[mt][nt], afr[mt], bfr[nt]);
        }

        if (more) {
            float* asd = AsBase + (buf ^ 1) * GA;
            float* bsd = BsBase + (buf ^ 1) * GB;
            *reinterpret_cast<float4*>(asd + lr * BKS + lc) = tf32r4(pa);
            *reinterpret_cast<float4*>(bsd + lr * BKS + lc) = tf32r4(pb0);
            *reinterpret_cast<float4*>(bsd + (lr + 128) * BKS + lc) = tf32r4(pb1);
        }
    }

#pragma unroll
    for (int mt = 0; mt < 2; mt++) {
        const int row0 = m0 + wm * 32 + mt * 16 + g;
#pragma unroll
        for (int nt = 0; nt < 8; nt++) {
            const int col = n0 + wn * 64 + nt * 8 + 2 * t;
            const float b0 = bias[col], b1 = bias[col + 1];
            float* c0 = C + (size_t)row0 * HID + col;
            float* c1 = C + (size_t)(row0 + 8) * HID + col;
            c0[0] = acc[mt][nt][0] + b0; c0[1] = acc[mt][nt][1] + b1;
            c1[0] = acc[mt][nt][2] + b0; c1[1] = acc[mt][nt][3] + b1;
        }
    }
}

__global__ __launch_bounds__(512, 1) void gemm_qkv(
    const float* __restrict__ q_in, const float* __restrict__ k_in,
    const float* __restrict__ v_in,
    const float* __restrict__ Wq, const float* __restrict__ bq,
    const float* __restrict__ Wk, const float* __restrict__ bk,
    const float* __restrict__ Wv, const float* __restrict__ bv)
{
    if (blockIdx.z == 0)      gemm_body(q_in, Wq, bq, g_Q);
    else if (blockIdx.z == 1) gemm_body(k_in, Wk, bk, g_K);
    else                      gemm_body(v_in, Wv, bv, g_V);
}

__global__ __launch_bounds__(512, 1) void gemm_out(
    const float* __restrict__ W, const float* __restrict__ bias,
    float* __restrict__ C)
{
    gemm_body(g_X, W, bias, C);
}

// =====================================================================
// Fused MMA attention (R7 v3 + dual-accumulator ILP in w1/w2):
// Q frags in regs, K/V register-prefetched. block = (32 q, h, b),
// 512 threads, 16 warps.
//
// SMEM layout (float offsets):
//  sQ  @ 0      [32][68]            (union w/ sSb [32][136] later)
//  sP  @ 2176   [32][132]
//  sKV @ 6400   table_k[136][68] -> K halves [256][68] -> V halves [256][72]
//               -> table_v [136][72]
//  sS  @ 24832  [32][516]  logits / attn
//  sF  @ 41344  [32][516] bytes (final_mat as uchar)
// =====================================================================
constexpr int OFF_P  = 2176;
constexpr int OFF_KV = 6400;
constexpr int OFF_S  = 24832;
constexpr int OFF_F  = 41344;
constexpr int SMF_TOTAL = OFF_F + 4128;
constexpr size_t SMF_BYTES = (size_t)SMF_TOTAL * 4;  // 181,888 B

__global__ __launch_bounds__(512) void attn_fused_mma(
    const int* __restrict__ fm,
    const float* __restrict__ table_k,
    const float* __restrict__ table_v)
{
    extern __shared__ float smem[];
    float* sQ  = smem;                 // [32][68]
    float* sP  = smem + OFF_P;         // [32][132]
    float* sSb = smem;                 // [32][136] union
    float* sKV = smem + OFF_KV;
    float* sS  = smem + OFF_S;         // [32][516]
    unsigned char* sFb = reinterpret_cast<unsigned char*>(smem + OFF_F);

    const int tid  = threadIdx.x;
    const int lane = tid & 31;
    const int warp = tid >> 5;
    const int g    = lane >> 2;
    const int t    = lane & 3;
    const int mh   = warp >> 3;        // 0..1
    const int wg   = warp & 7;         // 0..7
    const int mr   = mh * 16;
    const int q0   = blockIdx.x * 32;
    const int h    = blockIdx.y;
    const int b    = blockIdx.z;

    // prefetch-index mapping (8 float4 per thread covers a 256-row half)
    const int pr  = tid >> 4;          // base row 0..31 (advances by 32)
    const int psg = (tid & 15) * 4;    // float offset in row
    const float* gKb = g_K + (size_t)(b * L) * HID + h * HD;
    const float* gVb = g_V + (size_t)(b * L) * HID + h * HD;

    // ---------- stage 0: stage Q (tf32), table_k (tf32, padded), fm ----------
    {
        const int q = tid >> 4;
        const int dbase = (tid & 15) * 4;
        float4 v = *reinterpret_cast<const float4*>(
            g_Q + (size_t)(b * L + q0 + q) * HID + h * HD + dbase);
        *reinterpret_cast<float4*>(sQ + q * 68 + dbase) = tf32r4(v);
    }
    for (int i = tid; i < 136 * 16; i += 512) {
        const int r = i >> 4, sg = (i & 15) * 4;
        float4 v = make_float4(0.f, 0.f, 0.f, 0.f);
        if (r < TAB) v = *reinterpret_cast<const float4*>(table_k + r * 64 + sg);
        *reinterpret_cast<float4*>(sKV + r * 68 + sg) = tf32r4(v);
    }
    for (int i = tid; i < 32 * 128; i += 512) {
        const int q = i >> 7;
        const int kq = (i & 127) * 4;
        const int4 v = *reinterpret_cast<const int4*>(
            fm + (size_t)(b * L + q0 + q) * L + kq);
        uchar4 pk = make_uchar4((unsigned char)v.x, (unsigned char)v.y,
                                (unsigned char)v.z, (unsigned char)v.w);
        *reinterpret_cast<uchar4*>(sFb + q * 516 + kq) = pk;
    }

    // issue K half-0 global loads now (consumed after P stage)
    float4 pf[8];
#pragma unroll
    for (int j = 0; j < 8; j++)
        pf[j] = *reinterpret_cast<const float4*>(
            gKb + (size_t)(pr + 32 * j) * HID + psg);

    __syncthreads();

    // ---------- Q fragments into registers ----------
    float qf[8][4];
#pragma unroll
    for (int ks = 0; ks < 8; ks++) {
        const int kb = ks * 8;
        qf[ks][0] = sQ[(mr + g    ) * 68 + kb + t];
        qf[ks][1] = sQ[(mr + g + 8) * 68 + kb + t];
        qf[ks][2] = sQ[(mr + g    ) * 68 + kb + t + 4];
        qf[ks][3] = sQ[(mr + g + 8) * 68 + kb + t + 4];
    }

    // ---------- stage 1: P[32][129] = Q @ table_k^T ----------
#pragma unroll
    for (int j = 0; j < 3; j++) {
        const int n8 = wg + 8 * j;
        if (n8 > 16) break;
        const int nb = n8 * 8;
        float acc[4] = {0.f, 0.f, 0.f, 0.f};
#pragma unroll
        for (int ks = 0; ks < 8; ks++) {
            const int kb = ks * 8;
            float bb[2];
            bb[0] = sKV[(nb + g) * 68 + kb + t];
            bb[1] = sKV[(nb + g) * 68 + kb + t + 4];
            mma_tf32(acc, qf[ks], bb);
        }
        const int c0 = nb + 2 * t;
        if (c0 < TAB) {
            sP[(mr + g    ) * 132 + c0] = acc[0];
            sP[(mr + g + 8) * 132 + c0] = acc[2];
        }
        if (c0 + 1 < TAB) {
            sP[(mr + g    ) * 132 + c0 + 1] = acc[1];
            sP[(mr + g + 8) * 132 + c0 + 1] = acc[3];
        }
    }
    __syncthreads();   // table_k region dead

    // ---------- scores: half 0 staging ----------
#pragma unroll
    for (int j = 0; j < 8; j++)
        *reinterpret_cast<float4*>(sKV + (pr + 32 * j) * 68 + psg) = tf32r4(pf[j]);
#pragma unroll
    for (int j = 0; j < 8; j++)
        pf[j] = *reinterpret_cast<const float4*>(
            gKb + (size_t)(256 + pr + 32 * j) * HID + psg);
    __syncthreads();

#pragma unroll
    for (int half = 0; half < 2; half++) {
        float acc4[4][4];
#pragma unroll
        for (int j = 0; j < 4; j++)
#pragma unroll
            for (int r = 0; r < 4; r++) acc4[j][r] = 0.f;

#pragma unroll
        for (int ks = 0; ks < 8; ks++) {
            const int kb = ks * 8;
#pragma unroll
            for (int j = 0; j < 4; j++) {
                const int nb = (wg * 4 + j) * 8;
                float bb[2];
                bb[0] = sKV[(nb + g) * 68 + kb + t];
                bb[1] = sKV[(nb + g) * 68 + kb + t + 4];
                mma_tf32(acc4[j], qf[ks], bb);
            }
        }

#pragma unroll
        for (int j = 0; j < 4; j++) {
            const int nb = (wg * 4 + j) * 8;
            const int row0 = mr + g, row1 = row0 + 8;
            const int kc = half * 256 + nb + 2 * t;
            const int t00 = sFb[row0 * 516 + kc], t01 = sFb[row0 * 516 + kc + 1];
            const int t10 = sFb[row1 * 516 + kc], t11 = sFb[row1 * 516 + kc + 1];
            sS[row0 * 516 + kc    ] = (acc4[j][0] + sP[row0 * 132 + t00]) * 0.125f;
            sS[row0 * 516 + kc + 1] = (acc4[j][1] + sP[row0 * 132 + t01]) * 0.125f;
            sS[row1 * 516 + kc    ] = (acc4[j][2] + sP[row1 * 132 + t10]) * 0.125f;
            sS[row1 * 516 + kc + 1] = (acc4[j][3] + sP[row1 * 132 + t11]) * 0.125f;
        }
        __syncthreads();

        if (half == 0) {
            // store K1, issue V0 loads
#pragma unroll
            for (int j = 0; j < 8; j++)
                *reinterpret_cast<float4*>(sKV + (pr + 32 * j) * 68 + psg) = tf32r4(pf[j]);
#pragma unroll
            for (int j = 0; j < 8; j++)
                pf[j] = *reinterpret_cast<const float4*>(
                    gVb + (size_t)(pr + 32 * j) * HID + psg);
            __syncthreads();
        }
    }

    // ---------- softmax (16 warps x 2 rows) + zero buckets ----------
    for (int r = warp * 2; r < warp * 2 + 2; r++) {
        float* row = sS + r * 516;
        float m = -1e30f;
#pragma unroll
        for (int i = 0; i < 16; i++) m = fmaxf(m, row[lane + 32 * i]);
#pragma unroll
        for (int o = 16; o > 0; o >>= 1) m = fmaxf(m, __shfl_xor_sync(0xffffffffu, m, o));
        float e[16];
        float s = 0.f;
#pragma unroll
        for (int i = 0; i < 16; i++) {
            e[i] = __expf(row[lane + 32 * i] - m);
            s += e[i];
        }
#pragma unroll
        for (int o = 16; o > 0; o >>= 1) s += __shfl_xor_sync(0xffffffffu, s, o);
        const float inv = 1.f / s;
#pragma unroll
        for (int i = 0; i < 16; i++) row[lane + 32 * i] = tf32r(e[i] * inv);
    }
    for (int i = tid; i < 32 * 136; i += 512) sSb[i] = 0.f;
    __syncthreads();

    // ---------- w1 = attn @ V, V prefetch pipeline, dual accumulators ----------
    const int nbw = wg * 8;
    float acc1a[4] = {0.f, 0.f, 0.f, 0.f};
    float acc1b[4] = {0.f, 0.f, 0.f, 0.f};
#pragma unroll
    for (int half = 0; half < 2; half++) {
        // store prefetched V half; on half 0, issue V1 loads
#pragma unroll
        for (int j = 0; j < 8; j++)
            *reinterpret_cast<float4*>(sKV + (pr + 32 * j) * 72 + psg) = tf32r4(pf[j]);
        if (half == 0) {
#pragma unroll
            for (int j = 0; j < 8; j++)
                pf[j] = *reinterpret_cast<const float4*>(
                    gVb + (size_t)(256 + pr + 32 * j) * HID + psg);
        }
        __syncthreads();

        const float* aS = sS + half * 256;
#pragma unroll
        for (int ks = 0; ks < 32; ks += 2) {
            // even k-step -> acc1a
            {
                const int kb = ks * 8;
                float a[4], bb[2];
                a[0] = aS[(mr + g    ) * 516 + kb + t];
                a[1] = aS[(mr + g + 8) * 516 + kb + t];
                a[2] = aS[(mr + g    ) * 516 + kb + t + 4];
                a[3] = aS[(mr + g + 8) * 516 + kb + t + 4];
                bb[0] = sKV[(kb + t    ) * 72 + nbw + g];
                bb[1] = sKV[(kb + t + 4) * 72 + nbw + g];
                mma_tf32(acc1a, a, bb);
            }
            // odd k-step -> acc1b (independent chain)
            {
                const int kb = (ks + 1) * 8;
                float a[4], bb[2];
                a[0] = aS[(mr + g    ) * 516 + kb + t];
                a[1] = aS[(mr + g + 8) * 516 + kb + t];
                a[2] = aS[(mr + g    ) * 516 + kb + t + 4];
                a[3] = aS[(mr + g + 8) * 516 + kb + t + 4];
                bb[0] = sKV[(kb + t    ) * 72 + nbw + g];
                bb[1] = sKV[(kb + t + 4) * 72 + nbw + g];
                mma_tf32(acc1b, a, bb);
            }
        }
        __syncthreads();
    }

    // ---------- bucket scatter + stage table_v ----------
    {
        const int q  = tid >> 4;
        const int kg = tid & 15;
        const unsigned char* fr = sFb + q * 516;
        const float* ar = sS + q * 516;
        float* sbq = sSb + q * 136;
#pragma unroll 4
        for (int i = 0; i < 32; i++) {
            const int k = i * 16 + kg;
            atomicAdd(&sbq[fr[k]], ar[k]);
        }
    }
    for (int i = tid; i < 136 * 16; i += 512) {
        const int r = i >> 4, sg = (i & 15) * 4;
        float4 v = make_float4(0.f, 0.f, 0.f, 0.f);
        if (r < TAB) v = *reinterpret_cast<const float4*>(table_v + r * 64 + sg);
        *reinterpret_cast<float4*>(sKV + r * 72 + sg) = tf32r4(v);
    }
    __syncthreads();

    // ---------- w2 = buckets @ table_v (17 k-steps, dual accumulators) ----------
    float acc2a[4] = {0.f, 0.f, 0.f, 0.f};
    float acc2b[4] = {0.f, 0.f, 0.f, 0.f};
#pragma unroll
    for (int ks = 0; ks < 17; ks++) {
        const int kb = ks * 8;
        float a[4], bb[2];
        a[0] = tf32r(sSb[(mr + g    ) * 136 + kb + t]);
        a[1] = tf32r(sSb[(mr + g + 8) * 136 + kb + t]);
        a[2] = tf32r(sSb[(mr + g    ) * 136 + kb + t + 4]);
        a[3] = tf32r(sSb[(mr + g + 8) * 136 + kb + t + 4]);
        bb[0] = sKV[(kb + t    ) * 72 + nbw + g];
        bb[1] = sKV[(kb + t + 4) * 72 + nbw + g];
        if (ks & 1) mma_tf32(acc2b, a, bb);
        else        mma_tf32(acc2a, a, bb);
    }

    // ---------- store ----------
    {
        const int row0 = mr + g;
        const int col  = nbw + 2 * t;
        float2 o0 = make_float2(acc1a[0] + acc1b[0] + acc2a[0] + acc2b[0],
                                acc1a[1] + acc1b[1] + acc2a[1] + acc2b[1]);
        float2 o1 = make_float2(acc1a[2] + acc1b[2] + acc2a[2] + acc2b[2],
                                acc1a[3] + acc1b[3] + acc2a[3] + acc2b[3]);
        *reinterpret_cast<float2*>(
            g_X + (size_t)(b * L + q0 + row0) * HID + h * HD + col) = o0;
        *reinterpret_cast<float2*>(
            g_X + (size_t)(b * L + q0 + row0 + 8) * HID + h * HD + col) = o1;
    }
}

// =====================================================================
// launch
// =====================================================================
extern "C" void kernel_launch(void* const* d_in, const int* in_sizes, int n_in,
                              void* d_out, int out_size)
{
    const float* query   = (const float*)d_in[0];
    const float* key     = (const float*)d_in[1];
    const float* value   = (const float*)d_in[2];
    const int*   fm      = (const int*)  d_in[3];
    const float* Wq      = (const float*)d_in[4];
    const float* bq      = (const float*)d_in[5];
    const float* Wk      = (const float*)d_in[6];
    const float* bk      = (const float*)d_in[7];
    const float* Wv      = (const float*)d_in[8];
    const float* bv      = (const float*)d_in[9];
    const float* Wo      = (const float*)d_in[10];
    const float* bo      = (const float*)d_in[11];
    const float* table_k = (const float*)d_in[12];
    const float* table_v = (const float*)d_in[13];
    float* out = (float*)d_out;

    cudaFuncSetAttribute(attn_fused_mma,
                         cudaFuncAttributeMaxDynamicSharedMemorySize, (int)SMF_BYTES);
    cudaFuncSetAttribute(gemm_qkv,
                         cudaFuncAttributeMaxDynamicSharedMemorySize, (int)GEMM_SMEM);
    cudaFuncSetAttribute(gemm_out,
                         cudaFuncAttributeMaxDynamicSharedMemorySize, (int)GEMM_SMEM);

    const dim3 gqkv(HID / 256, BL / 128, 3);  // (4, 32, 3)
    gemm_qkv<<<gqkv, 512, GEMM_SMEM>>>(query, key, value, Wq, bq, Wk, bk, Wv, bv);

    const dim3 gattn(L / 32, H, B);  // (16, 16, 8)
    attn_fused_mma<<<gattn, 512, SMF_BYTES>>>(fm, table_k, table_v);

    const dim3 gout(HID / 256, BL / 128);  // (4, 32)
    gemm_out<<<gout, 512, GEMM_SMEM>>>(Wo, bo, out);
}

// round 11
// speedup vs baseline: 1.1961x; 1.0621x over previous
#include <cuda_runtime.h>
#include <cstdint>

// ---------------- problem constants ----------------
constexpr int B    = 8;
constexpr int L    = 512;
constexpr int HID  = 1024;
constexpr int H    = 16;
constexpr int HD   = 64;     // head dim
constexpr int TAB  = 129;    // 2*64+1 relative-position table rows
constexpr int BL   = B * L;  // 4096

// ---------------- device scratch ----------------
__device__ float g_Q[BL * HID];
__device__ float g_K[BL * HID];
__device__ float g_V[BL * HID];
__device__ float g_X[BL * HID];                 // w1+w2 merged
__device__ unsigned char g_fmb[(size_t)B * L * L];  // final_mat as uchar (2 MB)
__device__ float g_tk[136 * 68];                // table_k tf32-rounded, padded
__device__ float g_tv[136 * 72];                // table_v tf32-rounded, padded

// =====================================================================
// tf32 helpers
// =====================================================================
__device__ __forceinline__ float tf32r(float x) {
    unsigned y;
    asm("cvt.rna.tf32.f32 %0, %1;" : "=r"(y) : "f"(x));
    return __uint_as_float(y);
}

__device__ __forceinline__ float4 tf32r4(float4 v) {
    return make_float4(tf32r(v.x), tf32r(v.y), tf32r(v.z), tf32r(v.w));
}

__device__ __forceinline__ void mma_tf32(float d[4], const float a[4], const float b[2]) {
    unsigned const* A = reinterpret_cast<unsigned const*>(a);
    unsigned const* Bp = reinterpret_cast<unsigned const*>(b);
    asm volatile(
        "mma.sync.aligned.m16n8k8.row.col.f32.tf32.tf32.f32 "
        "{%0,%1,%2,%3}, {%4,%5,%6,%7}, {%8,%9}, {%0,%1,%2,%3};"
        : "+f"(d[0]), "+f"(d[1]), "+f"(d[2]), "+f"(d[3])
        : "r"(A[0]), "r"(A[1]), "r"(A[2]), "r"(A[3]),
          "r"(Bp[0]), "r"(Bp[1]));
}

// ---------------- cp.async helpers ----------------
__device__ __forceinline__ uint32_t smem_u32(const void* p) {
    uint32_t a;
    asm("{ .reg .u64 t; cvta.to.shared.u64 t, %1; cvt.u32.u64 %0, t; }"
        : "=r"(a) : "l"(p));
    return a;
}
#define CP_ASYNC16(dst, src) \
    asm volatile("cp.async.cg.shared.global [%0], [%1], 16;" \
                 :: "r"(dst), "l"(src) : "memory")
#define CP_COMMIT() asm volatile("cp.async.commit_group;" ::: "memory")
#define CP_WAIT0()  asm volatile("cp.async.wait_group 0;" ::: "memory")
#define CP_WAIT1()  asm volatile("cp.async.wait_group 1;" ::: "memory")

// =====================================================================
// Prep kernel: pack final_mat -> uchar; round+pad tables.
// =====================================================================
__global__ __launch_bounds__(256) void prep_kernel(
    const int* __restrict__ fm,
    const float* __restrict__ tk, const float* __restrict__ tv)
{
    if (blockIdx.x < 2048) {
        const int idx = blockIdx.x * 1024 + threadIdx.x * 4;
        const int4 v = *reinterpret_cast<const int4*>(fm + idx);
        *reinterpret_cast<uchar4*>(g_fmb + idx) =
            make_uchar4((unsigned char)v.x, (unsigned char)v.y,
                        (unsigned char)v.z, (unsigned char)v.w);
    } else {
        for (int i = threadIdx.x; i < 136 * 68; i += 256) {
            const int r = i / 68, c = i - r * 68;
            g_tk[i] = (r < TAB && c < 64) ? tf32r(tk[r * 64 + c]) : 0.f;
        }
        for (int i = threadIdx.x; i < 136 * 72; i += 256) {
            const int r = i / 72, c = i - r * 72;
            g_tv[i] = (r < TAB && c < 64) ? tf32r(tv[r * 64 + c]) : 0.f;
        }
    }
}

// =====================================================================
// GEMM v3 (R9): C[4096,1024] = A @ W^T + bias. 128x256x16 tiles, 512 thr,
// 16 warps (4m x 4n), warp tile 32x64, double-buffered smem.
// ROUND: store tf32-rounded outputs (for g_Q/g_K/g_V, consumed rounded).
// =====================================================================
constexpr int BKS = 20;
constexpr int GA  = 128 * BKS;
constexpr int GB  = 256 * BKS;
constexpr size_t GEMM_SMEM = (size_t)2 * (GA + GB) * 4;  // 61,440 B

template <bool ROUND>
__device__ __forceinline__ void gemm_body(
    const float* __restrict__ A, const float* __restrict__ W,
    const float* __restrict__ bias, float* __restrict__ C)
{
    extern __shared__ float dsm[];
    float* AsBase = dsm;
    float* BsBase = dsm + 2 * GA;

    const int tid  = threadIdx.x;
    const int m0   = blockIdx.y * 128;
    const int n0   = blockIdx.x * 256;
    const int lane = tid & 31;
    const int g    = lane >> 2;
    const int t    = lane & 3;
    const int warp = tid >> 5;
    const int wm   = warp >> 2;
    const int wn   = warp & 3;

    const int lr = tid >> 2;
    const int lc = (tid & 3) * 4;
    const float* Ap  = A + (size_t)(m0 + lr) * HID + lc;
    const float* Wp0 = W + (size_t)(n0 + lr) * HID + lc;
    const float* Wp1 = W + (size_t)(n0 + lr + 128) * HID + lc;

    float acc[2][8][4];
#pragma unroll
    for (int i = 0; i < 2; i++)
#pragma unroll
        for (int j = 0; j < 8; j++)
#pragma unroll
            for (int r = 0; r < 4; r++) acc[i][j][r] = 0.f;

    float4 pa, pb0, pb1;
    pa  = *reinterpret_cast<const float4*>(Ap);
    pb0 = *reinterpret_cast<const float4*>(Wp0);
    pb1 = *reinterpret_cast<const float4*>(Wp1);

    *reinterpret_cast<float4*>(AsBase + lr * BKS + lc) = tf32r4(pa);
    *reinterpret_cast<float4*>(BsBase + lr * BKS + lc) = tf32r4(pb0);
    *reinterpret_cast<float4*>(BsBase + (lr + 128) * BKS + lc) = tf32r4(pb1);

    int buf = 0;
    for (int k0 = 0; k0 < HID; k0 += 16, buf ^= 1) {
        __syncthreads();

        const bool more = (k0 + 16 < HID);
        if (more) {
            pa  = *reinterpret_cast<const float4*>(Ap  + k0 + 16);
            pb0 = *reinterpret_cast<const float4*>(Wp0 + k0 + 16);
            pb1 = *reinterpret_cast<const float4*>(Wp1 + k0 + 16);
        }

        const float* As = AsBase + buf * GA;
        const float* Bs = BsBase + buf * GB;
#pragma unroll
        for (int ks = 0; ks < 2; ks++) {
            const int kc = ks * 8 + t;
            float afr[2][4], bfr[8][2];
#pragma unroll
            for (int mt = 0; mt < 2; mt++) {
                const int r = wm * 32 + mt * 16 + g;
                afr[mt][0] = As[(r    ) * BKS + kc];
                afr[mt][1] = As[(r + 8) * BKS + kc];
                afr[mt][2] = As[(r    ) * BKS + kc + 4];
                afr[mt][3] = As[(r + 8) * BKS + kc + 4];
            }
#pragma unroll
            for (int nt = 0; nt < 8; nt++) {
                const int n = wn * 64 + nt * 8 + g;
                bfr[nt][0] = Bs[n * BKS + kc];
                bfr[nt][1] = Bs[n * BKS + kc + 4];
            }
#pragma unroll
            for (int mt = 0; mt < 2; mt++)
#pragma unroll
                for (int nt = 0; nt < 8; nt++)
                    mma_tf32(acc[mt][nt], afr[mt], bfr[nt]);
        }

        if (more) {
            float* asd = AsBase + (buf ^ 1) * GA;
            float* bsd = BsBase + (buf ^ 1) * GB;
            *reinterpret_cast<float4*>(asd + lr * BKS + lc) = tf32r4(pa);
            *reinterpret_cast<float4*>(bsd + lr * BKS + lc) = tf32r4(pb0);
            *reinterpret_cast<float4*>(bsd + (lr + 128) * BKS + lc) = tf32r4(pb1);
        }
    }

#pragma unroll
    for (int mt = 0; mt < 2; mt++) {
        const int row0 = m0 + wm * 32 + mt * 16 + g;
#pragma unroll
        for (int nt = 0; nt < 8; nt++) {
            const int col = n0 + wn * 64 + nt * 8 + 2 * t;
            const float b0 = bias[col], b1 = bias[col + 1];
            float* c0 = C + (size_t)row0 * HID + col;
            float* c1 = C + (size_t)(row0 + 8) * HID + col;
            if (ROUND) {
                c0[0] = tf32r(acc[mt][nt][0] + b0); c0[1] = tf32r(acc[mt][nt][1] + b1);
                c1[0] = tf32r(acc[mt][nt][2] + b0); c1[1] = tf32r(acc[mt][nt][3] + b1);
            } else {
                c0[0] = acc[mt][nt][0] + b0; c0[1] = acc[mt][nt][1] + b1;
                c1[0] = acc[mt][nt][2] + b0; c1[1] = acc[mt][nt][3] + b1;
            }
        }
    }
}

__global__ __launch_bounds__(512, 1) void gemm_qkv(
    const float* __restrict__ q_in, const float* __restrict__ k_in,
    const float* __restrict__ v_in,
    const float* __restrict__ Wq, const float* __restrict__ bq,
    const float* __restrict__ Wk, const float* __restrict__ bk,
    const float* __restrict__ Wv, const float* __restrict__ bv)
{
    if (blockIdx.z == 0)      gemm_body<true>(q_in, Wq, bq, g_Q);
    else if (blockIdx.z == 1) gemm_body<true>(k_in, Wk, bk, g_K);
    else                      gemm_body<true>(v_in, Wv, bv, g_V);
}

__global__ __launch_bounds__(512, 1) void gemm_out(
    const float* __restrict__ W, const float* __restrict__ bias,
    float* __restrict__ C)
{
    gemm_body<false>(g_X, W, bias, C);
}

// =====================================================================
// Fused MMA attention v5: all staging via cp.async (inputs pre-rounded),
// K/V in double-buffered 128-row tiles, table_v load hidden under scatter.
// block = (32 q, h, b), 512 threads, 16 warps.
//
// SMEM (float offsets):
//  sQ  @ 0      [32][68]            (union w/ sSb [32][136])
//  sP  @ 2176   [32][132]
//  sKV @ 6400   18432 floats: table_k[136][68] -> K dbuf 2x[128][68]
//               -> V dbuf 2x[128][72] -> table_v [136][72]
//  sS  @ 24832  [32][516]
//  sF  @ 41344  [32] rows x 528 bytes (uchar, 16B-aligned rows)
// =====================================================================
constexpr int OFF_P  = 2176;
constexpr int OFF_KV = 6400;
constexpr int OFF_S  = 24832;
constexpr int OFF_F  = 41344;
constexpr int SMF_TOTAL = OFF_F + (32 * 528) / 4;       // 45568 floats
constexpr size_t SMF_BYTES = (size_t)SMF_TOTAL * 4;     // 182,272 B

__global__ __launch_bounds__(512) void attn_fused_mma()
{
    extern __shared__ float smem[];
    float* sQ  = smem;                 // [32][68]
    float* sP  = smem + OFF_P;         // [32][132]
    float* sSb = smem;                 // [32][136] union
    float* sKV = smem + OFF_KV;
    float* sS  = smem + OFF_S;         // [32][516]
    unsigned char* sFb = reinterpret_cast<unsigned char*>(smem + OFF_F);

    const uint32_t sbase = smem_u32(smem);
    const uint32_t sQa  = sbase;
    const uint32_t sKVa = sbase + OFF_KV * 4;
    const uint32_t sFa  = sbase + OFF_F * 4;

    const int tid  = threadIdx.x;
    const int lane = tid & 31;
    const int warp = tid >> 5;
    const int g    = lane >> 2;
    const int t    = lane & 3;
    const int mh   = warp >> 3;        // 0..1
    const int wg   = warp & 7;         // 0..7
    const int mr   = mh * 16;
    const int q0   = blockIdx.x * 32;
    const int h    = blockIdx.y;
    const int b    = blockIdx.z;

    const float* gKb = g_K + (size_t)(b * L) * HID + h * HD;
    const float* gVb = g_V + (size_t)(b * L) * HID + h * HD;

    // ---------- stage 0: cp.async Q, table_k, fm ----------
    {
        const int q = tid >> 4, seg = tid & 15;
        CP_ASYNC16(sQa + (uint32_t)(q * 68 + seg * 4) * 4,
                   g_Q + (size_t)(b * L + q0 + q) * HID + h * HD + seg * 4);
    }
    for (int i = tid; i < (136 * 68) / 4; i += 512)
        CP_ASYNC16(sKVa + (uint32_t)i * 16, g_tk + i * 4);
    for (int i = tid; i < 32 * 32; i += 512) {
        const int q = i >> 5, seg = i & 31;
        CP_ASYNC16(sFa + (uint32_t)(q * 528 + seg * 16),
                   g_fmb + (size_t)(b * L + q0 + q) * L + seg * 16);
    }
    CP_COMMIT();
    CP_WAIT0();
    __syncthreads();

    // ---------- Q fragments into registers ----------
    float qf[8][4];
#pragma unroll
    for (int ks = 0; ks < 8; ks++) {
        const int kb = ks * 8;
        qf[ks][0] = sQ[(mr + g    ) * 68 + kb + t];
        qf[ks][1] = sQ[(mr + g + 8) * 68 + kb + t];
        qf[ks][2] = sQ[(mr + g    ) * 68 + kb + t + 4];
        qf[ks][3] = sQ[(mr + g + 8) * 68 + kb + t + 4];
    }

    // ---------- P[32][129] = Q @ table_k^T ----------
#pragma unroll
    for (int j = 0; j < 3; j++) {
        const int n8 = wg + 8 * j;
        if (n8 > 16) break;
        const int nb = n8 * 8;
        float acc[4] = {0.f, 0.f, 0.f, 0.f};
#pragma unroll
        for (int ks = 0; ks < 8; ks++) {
            const int kb = ks * 8;
            float bb[2];
            bb[0] = sKV[(nb + g) * 68 + kb + t];
            bb[1] = sKV[(nb + g) * 68 + kb + t + 4];
            mma_tf32(acc, qf[ks], bb);
        }
        const int c0 = nb + 2 * t;
        if (c0 < TAB) {
            sP[(mr + g    ) * 132 + c0] = acc[0];
            sP[(mr + g + 8) * 132 + c0] = acc[2];
        }
        if (c0 + 1 < TAB) {
            sP[(mr + g    ) * 132 + c0 + 1] = acc[1];
            sP[(mr + g + 8) * 132 + c0 + 1] = acc[3];
        }
    }
    __syncthreads();   // table_k reads complete

    // ---------- issue K tile 0 ----------
#pragma unroll
    for (int j = 0; j < 4; j++) {
        const int idx = tid + 512 * j, row = idx >> 4, seg = idx & 15;
        CP_ASYNC16(sKVa + (uint32_t)(row * 68 + seg * 4) * 4,
                   gKb + (size_t)row * HID + seg * 4);
    }
    CP_COMMIT();

    // ---------- scores: 4 K-tiles of 128, double-buffered ----------
#pragma unroll 1
    for (int kt = 0; kt < 4; kt++) {
        if (kt < 3) {
            const uint32_t dstb = sKVa + (uint32_t)(((kt + 1) & 1) * 8704) * 4;
#pragma unroll
            for (int j = 0; j < 4; j++) {
                const int idx = tid + 512 * j, row = idx >> 4, seg = idx & 15;
                CP_ASYNC16(dstb + (uint32_t)(row * 68 + seg * 4) * 4,
                           gKb + (size_t)((kt + 1) * 128 + row) * HID + seg * 4);
            }
            CP_COMMIT();
            CP_WAIT1();
        } else {
            CP_WAIT0();
        }
        __syncthreads();

        const float* Kb = sKV + (kt & 1) * 8704;
#pragma unroll
        for (int jj = 0; jj < 2; jj++) {
            const int nb = (wg * 2 + jj) * 8;
            float acc[4] = {0.f, 0.f, 0.f, 0.f};
#pragma unroll
            for (int ks = 0; ks < 8; ks++) {
                const int kb = ks * 8;
                float bb[2];
                bb[0] = Kb[(nb + g) * 68 + kb + t];
                bb[1] = Kb[(nb + g) * 68 + kb + t + 4];
                mma_tf32(acc, qf[ks], bb);
            }
            const int row0 = mr + g, row1 = row0 + 8;
            const int kc = kt * 128 + nb + 2 * t;
            const int t00 = sFb[row0 * 528 + kc], t01 = sFb[row0 * 528 + kc + 1];
            const int t10 = sFb[row1 * 528 + kc], t11 = sFb[row1 * 528 + kc + 1];
            sS[row0 * 516 + kc    ] = (acc[0] + sP[row0 * 132 + t00]) * 0.125f;
            sS[row0 * 516 + kc + 1] = (acc[1] + sP[row0 * 132 + t01]) * 0.125f;
            sS[row1 * 516 + kc    ] = (acc[2] + sP[row1 * 132 + t10]) * 0.125f;
            sS[row1 * 516 + kc + 1] = (acc[3] + sP[row1 * 132 + t11]) * 0.125f;
        }
        __syncthreads();
    }

    // ---------- issue V tile 0 (hides under softmax) ----------
#pragma unroll
    for (int j = 0; j < 4; j++) {
        const int idx = tid + 512 * j, row = idx >> 4, seg = idx & 15;
        CP_ASYNC16(sKVa + (uint32_t)(row * 72 + seg * 4) * 4,
                   gVb + (size_t)row * HID + seg * 4);
    }
    CP_COMMIT();

    // ---------- softmax (16 warps x 2 rows) + zero buckets ----------
    for (int r = warp * 2; r < warp * 2 + 2; r++) {
        float* row = sS + r * 516;
        float m = -1e30f;
#pragma unroll
        for (int i = 0; i < 16; i++) m = fmaxf(m, row[lane + 32 * i]);
#pragma unroll
        for (int o = 16; o > 0; o >>= 1) m = fmaxf(m, __shfl_xor_sync(0xffffffffu, m, o));
        float e[16];
        float s = 0.f;
#pragma unroll
        for (int i = 0; i < 16; i++) {
            e[i] = __expf(row[lane + 32 * i] - m);
            s += e[i];
        }
#pragma unroll
        for (int o = 16; o > 0; o >>= 1) s += __shfl_xor_sync(0xffffffffu, s, o);
        const float inv = 1.f / s;
#pragma unroll
        for (int i = 0; i < 16; i++) row[lane + 32 * i] = tf32r(e[i] * inv);
    }
    for (int i = tid; i < 32 * 136; i += 512) sSb[i] = 0.f;
    CP_WAIT0();
    __syncthreads();

    // ---------- w1 = attn @ V: 4 V-tiles of 128, double-buffered ----------
    const int nbw = wg * 8;
    float acc1a[4] = {0.f, 0.f, 0.f, 0.f};
    float acc1b[4] = {0.f, 0.f, 0.f, 0.f};
#pragma unroll 1
    for (int vt = 0; vt < 4; vt++) {
        if (vt < 3) {
            const uint32_t dstb = sKVa + (uint32_t)(((vt + 1) & 1) * 9216) * 4;
#pragma unroll
            for (int j = 0; j < 4; j++) {
                const int idx = tid + 512 * j, row = idx >> 4, seg = idx & 15;
                CP_ASYNC16(dstb + (uint32_t)(row * 72 + seg * 4) * 4,
                           gVb + (size_t)((vt + 1) * 128 + row) * HID + seg * 4);
            }
            CP_COMMIT();
            CP_WAIT1();
        } else {
            CP_WAIT0();
        }
        __syncthreads();

        const float* Vb = sKV + (vt & 1) * 9216;
        const int cb = vt * 128;
#pragma unroll
        for (int ks = 0; ks < 16; ks += 2) {
            {
                const int kb = ks * 8;
                float a[4], bb[2];
                a[0] = sS[(mr + g    ) * 516 + cb + kb + t];
                a[1] = sS[(mr + g + 8) * 516 + cb + kb + t];
                a[2] = sS[(mr + g    ) * 516 + cb + kb + t + 4];
                a[3] = sS[(mr + g + 8) * 516 + cb + kb + t + 4];
                bb[0] = Vb[(kb + t    ) * 72 + nbw + g];
                bb[1] = Vb[(kb + t + 4) * 72 + nbw + g];
                mma_tf32(acc1a, a, bb);
            }
            {
                const int kb = (ks + 1) * 8;
                float a[4], bb[2];
                a[0] = sS[(mr + g    ) * 516 + cb + kb + t];
                a[1] = sS[(mr + g + 8) * 516 + cb + kb + t];
                a[2] = sS[(mr + g    ) * 516 + cb + kb + t + 4];
                a[3] = sS[(mr + g + 8) * 516 + cb + kb + t + 4];
                bb[0] = Vb[(kb + t    ) * 72 + nbw + g];
                bb[1] = Vb[(kb + t + 4) * 72 + nbw + g];
                mma_tf32(acc1b, a, bb);
            }
        }
        __syncthreads();
    }

    // ---------- issue table_v (hides under scatter) ----------
    for (int i = tid; i < (136 * 72) / 4; i += 512)
        CP_ASYNC16(sKVa + (uint32_t)i * 16, g_tv + i * 4);
    CP_COMMIT();

    // ---------- bucket scatter ----------
    {
        const int q  = tid >> 4;
        const int kg = tid & 15;
        const unsigned char* fr = sFb + q * 528;
        const float* ar = sS + q * 516;
        float* sbq = sSb + q * 136;
#pragma unroll 4
        for (int i = 0; i < 32; i++) {
            const int k = i * 16 + kg;
            atomicAdd(&sbq[fr[k]], ar[k]);
        }
    }
    CP_WAIT0();
    __syncthreads();

    // ---------- w2 = buckets @ table_v (17 k-steps, dual accumulators) ----------
    float acc2a[4] = {0.f, 0.f, 0.f, 0.f};
    float acc2b[4] = {0.f, 0.f, 0.f, 0.f};
#pragma unroll
    for (int ks = 0; ks < 17; ks++) {
        const int kb = ks * 8;
        float a[4], bb[2];
        a[0] = tf32r(sSb[(mr + g    ) * 136 + kb + t]);
        a[1] = tf32r(sSb[(mr + g + 8) * 136 + kb + t]);
        a[2] = tf32r(sSb[(mr + g    ) * 136 + kb + t + 4]);
        a[3] = tf32r(sSb[(mr + g + 8) * 136 + kb + t + 4]);
        bb[0] = sKV[(kb + t    ) * 72 + nbw + g];
        bb[1] = sKV[(kb + t + 4) * 72 + nbw + g];
        if (ks & 1) mma_tf32(acc2b, a, bb);
        else        mma_tf32(acc2a, a, bb);
    }

    // ---------- store ----------
    {
        const int row0 = mr + g;
        const int col  = nbw + 2 * t;
        float2 o0 = make_float2(acc1a[0] + acc1b[0] + acc2a[0] + acc2b[0],
                                acc1a[1] + acc1b[1] + acc2a[1] + acc2b[1]);
        float2 o1 = make_float2(acc1a[2] + acc1b[2] + acc2a[2] + acc2b[2],
                                acc1a[3] + acc1b[3] + acc2a[3] + acc2b[3]);
        *reinterpret_cast<float2*>(
            g_X + (size_t)(b * L + q0 + row0) * HID + h * HD + col) = o0;
        *reinterpret_cast<float2*>(
            g_X + (size_t)(b * L + q0 + row0 + 8) * HID + h * HD + col) = o1;
    }
}

// =====================================================================
// launch
// =====================================================================
extern "C" void kernel_launch(void* const* d_in, const int* in_sizes, int n_in,
                              void* d_out, int out_size)
{
    const float* query   = (const float*)d_in[0];
    const float* key     = (const float*)d_in[1];
    const float* value   = (const float*)d_in[2];
    const int*   fm      = (const int*)  d_in[3];
    const float* Wq      = (const float*)d_in[4];
    const float* bq      = (const float*)d_in[5];
    const float* Wk      = (const float*)d_in[6];
    const float* bk      = (const float*)d_in[7];
    const float* Wv      = (const float*)d_in[8];
    const float* bv      = (const float*)d_in[9];
    const float* Wo      = (const float*)d_in[10];
    const float* bo      = (const float*)d_in[11];
    const float* table_k = (const float*)d_in[12];
    const float* table_v = (const float*)d_in[13];
    float* out = (float*)d_out;

    cudaFuncSetAttribute(attn_fused_mma,
                         cudaFuncAttributeMaxDynamicSharedMemorySize, (int)SMF_BYTES);
    cudaFuncSetAttribute(gemm_qkv,
                         cudaFuncAttributeMaxDynamicSharedMemorySize, (int)GEMM_SMEM);
    cudaFuncSetAttribute(gemm_out,
                         cudaFuncAttributeMaxDynamicSharedMemorySize, (int)GEMM_SMEM);

    prep_kernel<<<2049, 256>>>(fm, table_k, table_v);

    const dim3 gqkv(HID / 256, BL / 128, 3);  // (4, 32, 3)
    gemm_qkv<<<gqkv, 512, GEMM_SMEM>>>(query, key, value, Wq, bq, Wk, bk, Wv, bv);

    const dim3 gattn(L / 32, H, B);  // (16, 16, 8)
    attn_fused_mma<<<gattn, 512, SMF_BYTES>>>();

    const dim3 gout(HID / 256, BL / 128);  // (4, 32)
    gemm_out<<<gout, 512, GEMM_SMEM>>>(Wo, bo, out);
}